// round 15
// baseline (speedup 1.0000x reference)
#include <cuda_runtime.h>

#define T_STEPS 2048
#define N_RES   2048
#define D_IN    128
#define NCTA    128
#define NTHR    512
#define ROWS_PER_CTA 16
#define INV_SQRT_N 0.022097086912079608f  // 1/sqrt(2048)
#define SENT32 0x7FC00000u                // qNaN sentinel bit pattern

// Scratch: precomputed input projections U[t][n] (16 MB).
__device__ float g_U[(size_t)T_STEPS * N_RES];

// Prefill out with qNaN sentinel: real x values are erf(..)/sqrt(N), never NaN.
__global__ void esn_prefill(float4* __restrict__ out4) {
    const float qn = __uint_as_float(SENT32);
    const float4 nv = make_float4(qn, qn, qn, qn);
    const size_t total = (size_t)T_STEPS * N_RES / 4;
    const size_t stride = (size_t)gridDim.x * blockDim.x;
    for (size_t i = (size_t)blockIdx.x * blockDim.x + threadIdx.x; i < total; i += stride)
        out4[i] = nv;
}

__global__ void __launch_bounds__(NTHR, 1) esn_main(
    const float* __restrict__ input,   // [T, D]
    const float* __restrict__ W_in,    // [N, D]
    const float* __restrict__ W_res,   // [N, N]
    float* __restrict__ out)           // [T, N]  (row t == x_t)
{
    const int tid   = threadIdx.x;
    const int b     = blockIdx.x;
    const int rbase = b * ROWS_PER_CTA;
    const int l     = tid & 31;
    const int w     = tid >> 5;          // warp 0..15
    const int rowg  = w & 3;             // 4 row-groups of 4 rows
    const int colg  = w >> 2;            // 4 col-groups of 512 cols
    const int cbase = colg * 512;

    __shared__ float sh[2048];           // W_in slice (phase U only)
    __shared__ float part[2][16][4];     // [t&1][row][colg] -> LDS.128 combine

    // ================= Phase U: U = input @ W_in^T (own 16 columns) ============
    ((float4*)sh)[tid] = ((const float4*)(W_in + (size_t)rbase * D_IN))[tid];
    __syncthreads();

    for (int k = 0; k < 4; ++k) {
        const int t = tid + NTHR * k;
        float acc[16];
        #pragma unroll
        for (int n = 0; n < 16; ++n) acc[n] = 0.f;
        const float4* inrow = (const float4*)(input + (size_t)t * D_IN);
        for (int jd = 0; jd < 32; ++jd) {
            float4 iv = __ldg(inrow + jd);
            #pragma unroll
            for (int n = 0; n < 16; ++n) {
                float4 wv = ((const float4*)sh)[n * 32 + jd];
                acc[n] = fmaf(iv.x, wv.x, acc[n]);
                acc[n] = fmaf(iv.y, wv.y, acc[n]);
                acc[n] = fmaf(iv.z, wv.z, acc[n]);
                acc[n] = fmaf(iv.w, wv.w, acc[n]);
            }
        }
        float4* urow = (float4*)(g_U + (size_t)t * N_RES + rbase);
        #pragma unroll
        for (int q = 0; q < 4; ++q)
            urow[q] = make_float4(acc[4*q], acc[4*q+1], acc[4*q+2], acc[4*q+3]);
    }
    __syncthreads();

    // ============ Load recurrence weights into registers (64 floats/thread) ====
    unsigned long long wreg[4][8];
    #pragma unroll
    for (int i = 0; i < 4; ++i) {
        const float* wrow = W_res + (size_t)(rbase + rowg * 4 + i) * N_RES + cbase + 2 * l;
        #pragma unroll
        for (int j = 0; j < 8; ++j)
            wreg[i][j] = *(const unsigned long long*)(wrow + 64 * j);
    }

    // ================= t = 0: x0 = erf(U[0]) / sqrt(N) =========================
    if (w == 0 && l < 16) {
        float u0 = g_U[rbase + l];
        __stcg(&out[rbase + l], erff(u0) * INV_SQRT_N);
    }

    // ================= Recurrence ==============================================
    for (int t = 1; t < T_STEPS; ++t) {
        const int p = t & 1;
        float u = 0.f;
        if (w == 0 && l < 16) u = g_U[(size_t)t * N_RES + rbase + l];

        const float* xp = out + (size_t)(t - 1) * N_RES + cbase + 2 * l;

        // Speculative load (plain LDG: fresh lines; 4 warps/colgroup share L1).
        unsigned long long xr[8];
        #pragma unroll
        for (int j = 0; j < 8; ++j)
            xr[j] = *(const unsigned long long*)(xp + 64 * j);

        unsigned long long acc[4] = {0ull, 0ull, 0ull, 0ull};
        unsigned done = 0u;     // words already FMA'd into acc

        // Raw-bit sentinel classification (per 32-bit half: handles tearing);
        // FMA ready words immediately; retry ONLY stale words via L1-bypass.
        unsigned bad = 0u;
        #pragma unroll
        for (int j = 0; j < 8; ++j) {
            unsigned lo = (unsigned)xr[j], hi = (unsigned)(xr[j] >> 32);
            bad |= (unsigned)((lo == SENT32) | (hi == SENT32)) << j;
        }

        for (;;) {
            const unsigned newly = ~bad & ~done & 0xFFu;
            #pragma unroll
            for (int j = 0; j < 8; ++j) {
                if ((newly >> j) & 1u) {
                    #pragma unroll
                    for (int i = 0; i < 4; ++i)
                        asm volatile("fma.rn.f32x2 %0, %1, %2, %0;"
                                     : "+l"(acc[i]) : "l"(wreg[i][j]), "l"(xr[j]));
                }
            }
            done |= newly;
            if (!__any_sync(0xFFFFFFFFu, done != 0xFFu)) break;

            #pragma unroll
            for (int j = 0; j < 8; ++j) {
                if (bad & (1u << j))
                    asm volatile("ld.global.cg.b64 %0, [%1];"
                                 : "=l"(xr[j]) : "l"(xp + 64 * j) : "memory");
            }
            bad = 0u;
            #pragma unroll
            for (int j = 0; j < 8; ++j) {
                unsigned lo = (unsigned)xr[j], hi = (unsigned)(xr[j] >> 32);
                bad |= (unsigned)((lo == SENT32) | (hi == SENT32)) << j;
            }
        }

        float s[4];
        #pragma unroll
        for (int i = 0; i < 4; ++i) {
            float2 f = *reinterpret_cast<float2*>(&acc[i]);
            s[i] = f.x + f.y;
        }
        #pragma unroll
        for (int off = 16; off > 0; off >>= 1) {
            #pragma unroll
            for (int i = 0; i < 4; ++i)
                s[i] += __shfl_xor_sync(0xFFFFFFFFu, s[i], off);
        }
        if (l == 0) {
            #pragma unroll
            for (int i = 0; i < 4; ++i)
                part[p][rowg * 4 + i][colg] = s[i];
        }

        // Split barrier (named, parity id): warps 1-15 arrive and roll straight
        // into step t+1's speculative loads; warp 0 syncs, combines, stores.
        // Bounded skew (<=1 step) is enforced by the global data dependency,
        // so two parity ids are sufficient and part[] ping-pong is race-free.
        if (w == 0) {
            asm volatile("bar.sync %0, %1;" :: "r"(1 + p), "n"(NTHR) : "memory");
            if (l < 16) {
                float4 v = *(float4*)&part[p][l][0];   // single LDS.128
                float pre = v.x + v.y + v.z + v.w + u;
                __stcg(&out[(size_t)t * N_RES + rbase + l], erff(pre) * INV_SQRT_N);
            }
        } else {
            asm volatile("bar.arrive %0, %1;" :: "r"(1 + p), "n"(NTHR) : "memory");
        }
    }
}

extern "C" void kernel_launch(void* const* d_in, const int* in_sizes, int n_in,
                              void* d_out, int out_size)
{
    const float* input = (const float*)d_in[0];   // (2048, 128)
    const float* W_in  = (const float*)d_in[1];   // (2048, 128)
    const float* W_res = (const float*)d_in[2];   // (2048, 2048)
    float* out = (float*)d_out;                   // (2048, 2048)

    esn_prefill<<<NCTA, NTHR>>>((float4*)out);
    esn_main<<<NCTA, NTHR>>>(input, W_in, W_res, out);
}